// round 2
// baseline (speedup 1.0000x reference)
#include <cuda_runtime.h>
#include <cstdint>

#define USER_NUM 50000
#define ITEM_NUM 50000
#define NTOT     100000
#define VT_DIM   512
#define CAT_DIM  32
#define HID      128
#define OUTD     64

// ---------------- static scratch (no allocs allowed) ----------------
__device__ float g_x0[(size_t)NTOT * HID];    // [user; item_feat]
__device__ float g_h1[(size_t)NTOT * HID];    // x0 @ w1_l.T
__device__ float g_s1[(size_t)NTOT * HID];    // edge-aggregated sums (conv1)
__device__ float g_x1[(size_t)NTOT * HID];    // leaky(conv1)
__device__ float g_h2[(size_t)NTOT * OUTD];   // x1 @ w2_l.T
__device__ float g_s2[(size_t)NTOT * OUTD];   // edge-aggregated sums (conv2)
__device__ float g_cat[(size_t)ITEM_NUM * CAT_DIM];
__device__ float g_deg[NTOT];

// ---------------- helpers ----------------
__device__ __forceinline__ void red_add_v4(float* p, float4 v) {
    asm volatile("red.global.add.v4.f32 [%0], {%1, %2, %3, %4};"
                 :: "l"(p), "f"(v.x), "f"(v.y), "f"(v.z), "f"(v.w) : "memory");
}

// packed dual-fp32 FMA: d = a*b + d  (SASS FFMA2 — 2 fp32 FMAs per issue slot)
__device__ __forceinline__ void ffma2(unsigned long long& d,
                                      unsigned long long a,
                                      unsigned long long b) {
    asm("fma.rn.f32x2 %0, %1, %2, %0;" : "+l"(d) : "l"(a), "l"(b));
}
__device__ __forceinline__ void unpack2(unsigned long long v, float& lo, float& hi) {
    asm("mov.b64 {%0, %1}, %2;" : "=f"(lo), "=f"(hi) : "l"(v));
}

// ---------------- zero scratch ----------------
__global__ void zero_fill_kernel() {
    size_t n1 = (size_t)NTOT * HID / 4;   // g_s1 float4s
    size_t n2 = (size_t)NTOT * OUTD / 4;  // g_s2 float4s
    size_t stride = (size_t)gridDim.x * blockDim.x;
    size_t gid = (size_t)blockIdx.x * blockDim.x + threadIdx.x;
    float4 z = make_float4(0.f, 0.f, 0.f, 0.f);
    for (size_t i = gid; i < n1; i += stride) ((float4*)g_s1)[i] = z;
    for (size_t i = gid; i < n2; i += stride) ((float4*)g_s2)[i] = z;
    for (size_t i = gid; i < NTOT; i += stride) g_deg[i] = 0.f;
}

// ---------------- copy user rows into x0 ----------------
__global__ void copy_user_kernel(const float* __restrict__ user) {
    size_t n = (size_t)USER_NUM * HID / 4;
    size_t gid = (size_t)blockIdx.x * blockDim.x + threadIdx.x;
    if (gid < n) ((float4*)g_x0)[gid] = ((const float4*)user)[gid];
}

// ---------------- embedding bag (mean of ~5 rows of 32) ----------------
__global__ void catbag_kernel(const float* __restrict__ table,
                              const int* __restrict__ idx,
                              const int* __restrict__ offs,
                              int tot_idx) {
    int gid = blockIdx.x * blockDim.x + threadIdx.x;     // ITEM_NUM * 8 lanes
    if (gid >= ITEM_NUM * 8) return;
    int bag  = gid >> 3;
    int comp = (gid & 7) * 4;
    int beg = offs[bag];
    int end = (bag + 1 < ITEM_NUM) ? offs[bag + 1] : tot_idx;
    float4 s = make_float4(0.f, 0.f, 0.f, 0.f);
    for (int j = beg; j < end; j++) {
        int ix = __ldg(&idx[j]);
        float4 t = *(const float4*)(table + (size_t)ix * CAT_DIM + comp);
        s.x += t.x; s.y += t.y; s.z += t.z; s.w += t.w;
    }
    float inv = 1.0f / (float)max(end - beg, 1);
    s.x *= inv; s.y *= inv; s.z *= inv; s.w *= inv;
    *(float4*)(g_cat + (size_t)bag * CAT_DIM + comp) = s;
}

// ---------------- degree ----------------
__global__ void deg_kernel(const int* __restrict__ dst, int E) {
    int stride = gridDim.x * blockDim.x;
    for (int e = blockIdx.x * blockDim.x + threadIdx.x; e < E; e += stride)
        atomicAdd(&g_deg[__ldg(&dst[e])], 1.0f);
}

// ---------------- edge scatter: s[dst] += h[src], NC floats/row ----------------
template <int NC>
__global__ void scatter_kernel(const float* __restrict__ h,
                               const int* __restrict__ src,
                               const int* __restrict__ dst,
                               float* __restrict__ s, int E) {
    constexpr int LPE = NC / 4;                      // lanes per edge (32 or 16)
    int lane = threadIdx.x & (LPE - 1);
    int eg = (blockIdx.x * blockDim.x + threadIdx.x) / LPE;
    int estride = (gridDim.x * blockDim.x) / LPE;
    for (int e = eg; e < E; e += estride) {
        int si = __ldg(&src[e]);
        int di = __ldg(&dst[e]);
        float4 v = *(const float4*)(h + (size_t)si * NC + lane * 4);
        red_add_v4(s + (size_t)di * NC + lane * 4, v);
    }
}

// ---------------- tiled SIMT GEMM (FFMA2):  C[M,NC] = A[M,K] @ W[NC,K]^T ----
// EPI: 0 = plain, 1 = leaky(C + b + s/deg), 2 = C + b + s/deg
template <int NC, int EPI, bool FUSED>
__global__ __launch_bounds__(256)
void gemm_kernel(const float* __restrict__ A, int K,
                 const float* __restrict__ A2,          // cat part when FUSED
                 const float* __restrict__ W,
                 const float* __restrict__ bias,
                 const float* __restrict__ sagg,
                 const float* __restrict__ degp,
                 float* __restrict__ C, int M) {
    constexpr int BM = 64, BK = 32;
    constexpr int CPT = NC / 16;                       // cols per thread (8 or 4)
    constexpr int CP2 = CPT / 2;                       // packed col-pairs (4 or 2)
    constexpr int CQ  = CPT / 4;                       // ull2 W loads per k (2 or 1)
    __shared__ float AsD[BM][2 * BK + 4];              // value-duplicated A tile
    __shared__ float Ws[BK][NC + 4];                   // k-major W tile

    int tid = threadIdx.x;
    int tx = tid & 15, ty = tid >> 4;
    int row0 = blockIdx.x * BM;
    int r0 = ty * 4;
    int c0 = tx * CPT;

    unsigned long long acc2[4][CP2];
#pragma unroll
    for (int i = 0; i < 4; i++)
#pragma unroll
        for (int j = 0; j < CP2; j++) acc2[i][j] = 0ull;

    int nchunks = K / BK;
    for (int ch = 0; ch < nchunks; ch++) {
        int kk = ch * BK;
        // --- load A tile: 64x32 (2 float4/thread), store value-duplicated ---
        {
            int ar = tid >> 2;
            int kc = (tid & 3) * 8;
            int grow = row0 + ar;
            float4 v0 = make_float4(0, 0, 0, 0), v1 = v0;
            if (grow < M) {
                const float* base;
                int koff;
                if (!FUSED) { base = A + (size_t)grow * K; koff = kk + kc; }
                else if (kk < VT_DIM) { base = A + (size_t)grow * VT_DIM; koff = kk + kc; }
                else { base = A2 + (size_t)grow * CAT_DIM; koff = kk - VT_DIM + kc; }
                const float4* p = (const float4*)(base + koff);
                v0 = p[0]; v1 = p[1];
            }
            *(float4*)&AsD[ar][2 * kc + 0]  = make_float4(v0.x, v0.x, v0.y, v0.y);
            *(float4*)&AsD[ar][2 * kc + 4]  = make_float4(v0.z, v0.z, v0.w, v0.w);
            *(float4*)&AsD[ar][2 * kc + 8]  = make_float4(v1.x, v1.x, v1.y, v1.y);
            *(float4*)&AsD[ar][2 * kc + 12] = make_float4(v1.z, v1.z, v1.w, v1.w);
        }
        // --- load W tile: NC x 32, transposed into Ws[k][c] ---
        {
            constexpr int TOT = NC * 8;                // float4 count
#pragma unroll
            for (int j = 0; j < TOT / 256; j++) {
                int idx = j * 256 + tid;
                int c = idx >> 3;
                int kq = idx & 7;
                float4 w = *(const float4*)(W + (size_t)c * K + kk + kq * 4);
                Ws[kq * 4 + 0][c] = w.x;
                Ws[kq * 4 + 1][c] = w.y;
                Ws[kq * 4 + 2][c] = w.z;
                Ws[kq * 4 + 3][c] = w.w;
            }
        }
        __syncthreads();
        // --- compute: packed dual-fp32 FMAs ---
#pragma unroll 4
        for (int k2 = 0; k2 < BK; k2 += 2) {
            ulonglong2 aa[4];
#pragma unroll
            for (int i = 0; i < 4; i++)
                aa[i] = *(const ulonglong2*)&AsD[r0 + i][2 * k2];
            ulonglong2 wv0[CQ], wv1[CQ];
#pragma unroll
            for (int q = 0; q < CQ; q++) {
                wv0[q] = *(const ulonglong2*)&Ws[k2 + 0][c0 + q * 4];
                wv1[q] = *(const ulonglong2*)&Ws[k2 + 1][c0 + q * 4];
            }
#pragma unroll
            for (int i = 0; i < 4; i++) {
#pragma unroll
                for (int q = 0; q < CQ; q++) {
                    ffma2(acc2[i][2 * q + 0], aa[i].x, wv0[q].x);
                    ffma2(acc2[i][2 * q + 1], aa[i].x, wv0[q].y);
                    ffma2(acc2[i][2 * q + 0], aa[i].y, wv1[q].x);
                    ffma2(acc2[i][2 * q + 1], aa[i].y, wv1[q].y);
                }
            }
        }
        __syncthreads();
    }
    // --- epilogue ---
#pragma unroll
    for (int i = 0; i < 4; i++) {
        int gr = row0 + r0 + i;
        if (gr >= M) continue;
        float dinv = 0.f;
        if (EPI != 0) dinv = 1.0f / fmaxf(degp[gr], 1.0f);
#pragma unroll
        for (int q = 0; q < CQ; q++) {
            int gc = c0 + q * 4;
            float4 v;
            unpack2(acc2[i][2 * q + 0], v.x, v.y);
            unpack2(acc2[i][2 * q + 1], v.z, v.w);
            if (EPI != 0) {
                float4 sv = *(const float4*)(sagg + (size_t)gr * NC + gc);
                v.x += bias[gc + 0] + sv.x * dinv;
                v.y += bias[gc + 1] + sv.y * dinv;
                v.z += bias[gc + 2] + sv.z * dinv;
                v.w += bias[gc + 3] + sv.w * dinv;
                if (EPI == 1) {
                    v.x = v.x > 0.f ? v.x : 0.01f * v.x;
                    v.y = v.y > 0.f ? v.y : 0.01f * v.y;
                    v.z = v.z > 0.f ? v.z : 0.01f * v.z;
                    v.w = v.w > 0.f ? v.w : 0.01f * v.w;
                }
            }
            *(float4*)(C + (size_t)gr * NC + gc) = v;
        }
    }
}

// ---------------- launch ----------------
extern "C" void kernel_launch(void* const* d_in, const int* in_sizes, int n_in,
                              void* d_out, int out_size) {
    const float* vt      = (const float*)d_in[0];
    const int*   cat_idx = (const int*)d_in[1];
    const int*   cat_off = (const int*)d_in[2];
    const int*   edge    = (const int*)d_in[3];
    const float* cat_tab = (const float*)d_in[4];
    const float* fuse_w  = (const float*)d_in[5];
    const float* user    = (const float*)d_in[6];
    const float* w1_l    = (const float*)d_in[7];
    const float* b1      = (const float*)d_in[8];
    const float* w1_r    = (const float*)d_in[9];
    const float* w2_l    = (const float*)d_in[10];
    const float* b2      = (const float*)d_in[11];
    const float* w2_r    = (const float*)d_in[12];

    int E = in_sizes[3] / 2;
    const int* src = edge;
    const int* dst = edge + E;
    int tot_idx = in_sizes[1];

    float *x0p, *h1p, *s1p, *x1p, *h2p, *s2p, *catp, *degp;
    cudaGetSymbolAddress((void**)&x0p, g_x0);
    cudaGetSymbolAddress((void**)&h1p, g_h1);
    cudaGetSymbolAddress((void**)&s1p, g_s1);
    cudaGetSymbolAddress((void**)&x1p, g_x1);
    cudaGetSymbolAddress((void**)&h2p, g_h2);
    cudaGetSymbolAddress((void**)&s2p, g_s2);
    cudaGetSymbolAddress((void**)&catp, g_cat);
    cudaGetSymbolAddress((void**)&degp, g_deg);

    const int grid_item = (ITEM_NUM + 63) / 64;   // 782
    const int grid_all  = (NTOT + 63) / 64;       // 1563

    // 1. zero scratch
    zero_fill_kernel<<<2048, 256>>>();
    // 2. x0[0:USER] = user
    copy_user_kernel<<<(USER_NUM * HID / 4 + 255) / 256, 256>>>(user);
    // 3. cat embedding bag
    catbag_kernel<<<(ITEM_NUM * 8 + 255) / 256, 256>>>(cat_tab, cat_idx, cat_off, tot_idx);
    // 4. item_feat = [vt | cat] @ fuse_w.T  -> x0[USER:]
    gemm_kernel<128, 0, true><<<grid_item, 256>>>(
        vt, VT_DIM + CAT_DIM, catp, fuse_w, nullptr, nullptr, nullptr,
        x0p + (size_t)USER_NUM * HID, ITEM_NUM);
    // 5. degree
    deg_kernel<<<2048, 256>>>(dst, E);
    // 6. h1 = x0 @ w1_l.T
    gemm_kernel<128, 0, false><<<grid_all, 256>>>(
        x0p, HID, nullptr, w1_l, nullptr, nullptr, nullptr, h1p, NTOT);
    // 7. s1[dst] += h1[src]
    scatter_kernel<128><<<2048, 256>>>(h1p, src, dst, s1p, E);
    // 8. x1 = leaky(s1/deg + b1 + x0 @ w1_r.T)
    gemm_kernel<128, 1, false><<<grid_all, 256>>>(
        x0p, HID, nullptr, w1_r, b1, s1p, degp, x1p, NTOT);
    // 9. h2 = x1 @ w2_l.T
    gemm_kernel<64, 0, false><<<grid_all, 256>>>(
        x1p, HID, nullptr, w2_l, nullptr, nullptr, nullptr, h2p, NTOT);
    // 10. s2[dst] += h2[src]
    scatter_kernel<64><<<2048, 256>>>(h2p, src, dst, s2p, E);
    // 11. out = s2/deg + b2 + x1 @ w2_r.T
    gemm_kernel<64, 2, false><<<grid_all, 256>>>(
        x1p, HID, nullptr, w2_r, b2, s2p, degp, (float*)d_out, NTOT);
}

// round 3
// speedup vs baseline: 1.3661x; 1.3661x over previous
#include <cuda_runtime.h>
#include <cstdint>

#define USER_NUM 50000
#define ITEM_NUM 50000
#define NTOT     100000
#define VT_DIM   512
#define CAT_DIM  32
#define HID      128
#define OUTD     64

// ---------------- static scratch (no allocs allowed) ----------------
__device__ float g_x0[(size_t)NTOT * HID];    // [user; item_feat]
__device__ float g_h1[(size_t)NTOT * HID];    // x0 @ w1_l.T
__device__ float g_s1[(size_t)NTOT * HID];    // edge-aggregated sums (conv1)
__device__ float g_x1[(size_t)NTOT * HID];    // leaky(conv1)
__device__ float g_h2[(size_t)NTOT * OUTD];   // x1 @ w2_l.T
__device__ float g_s2[(size_t)NTOT * OUTD];   // edge-aggregated sums (conv2)
__device__ float g_cat[(size_t)ITEM_NUM * CAT_DIM];
__device__ float g_deg[NTOT];

// ---------------- helpers ----------------
__device__ __forceinline__ void red_add_v4(float* p, float4 v) {
    asm volatile("red.global.add.v4.f32 [%0], {%1, %2, %3, %4};"
                 :: "l"(p), "f"(v.x), "f"(v.y), "f"(v.z), "f"(v.w) : "memory");
}

// packed dual-fp32 FMA: d = a*b + d  (SASS FFMA2)
__device__ __forceinline__ void ffma2(unsigned long long& d,
                                      unsigned long long a,
                                      unsigned long long b) {
    asm("fma.rn.f32x2 %0, %1, %2, %0;" : "+l"(d) : "l"(a), "l"(b));
}
__device__ __forceinline__ unsigned long long pack_dup(float a) {
    unsigned long long r;
    asm("mov.b64 %0, {%1, %1};" : "=l"(r) : "f"(a));
    return r;
}
__device__ __forceinline__ void unpack2(unsigned long long v, float& lo, float& hi) {
    asm("mov.b64 {%0, %1}, %2;" : "=f"(lo), "=f"(hi) : "l"(v));
}

// ---------------- zero scratch ----------------
__global__ void zero_fill_kernel() {
    size_t n1 = (size_t)NTOT * HID / 4;
    size_t n2 = (size_t)NTOT * OUTD / 4;
    size_t stride = (size_t)gridDim.x * blockDim.x;
    size_t gid = (size_t)blockIdx.x * blockDim.x + threadIdx.x;
    float4 z = make_float4(0.f, 0.f, 0.f, 0.f);
    for (size_t i = gid; i < n1; i += stride) ((float4*)g_s1)[i] = z;
    for (size_t i = gid; i < n2; i += stride) ((float4*)g_s2)[i] = z;
    for (size_t i = gid; i < NTOT; i += stride) g_deg[i] = 0.f;
}

// ---------------- copy user rows into x0 ----------------
__global__ void copy_user_kernel(const float* __restrict__ user) {
    size_t n = (size_t)USER_NUM * HID / 4;
    size_t gid = (size_t)blockIdx.x * blockDim.x + threadIdx.x;
    if (gid < n) ((float4*)g_x0)[gid] = ((const float4*)user)[gid];
}

// ---------------- embedding bag (mean of ~5 rows of 32) ----------------
__global__ void catbag_kernel(const float* __restrict__ table,
                              const int* __restrict__ idx,
                              const int* __restrict__ offs,
                              int tot_idx) {
    int gid = blockIdx.x * blockDim.x + threadIdx.x;
    if (gid >= ITEM_NUM * 8) return;
    int bag  = gid >> 3;
    int comp = (gid & 7) * 4;
    int beg = offs[bag];
    int end = (bag + 1 < ITEM_NUM) ? offs[bag + 1] : tot_idx;
    float4 s = make_float4(0.f, 0.f, 0.f, 0.f);
    for (int j = beg; j < end; j++) {
        int ix = __ldg(&idx[j]);
        float4 t = *(const float4*)(table + (size_t)ix * CAT_DIM + comp);
        s.x += t.x; s.y += t.y; s.z += t.z; s.w += t.w;
    }
    float inv = 1.0f / (float)max(end - beg, 1);
    s.x *= inv; s.y *= inv; s.z *= inv; s.w *= inv;
    *(float4*)(g_cat + (size_t)bag * CAT_DIM + comp) = s;
}

// ---------------- degree ----------------
__global__ void deg_kernel(const int* __restrict__ dst, int E) {
    int stride = gridDim.x * blockDim.x;
    for (int e = blockIdx.x * blockDim.x + threadIdx.x; e < E; e += stride)
        atomicAdd(&g_deg[__ldg(&dst[e])], 1.0f);
}

// ---------------- edge scatter: s[dst] += h[src] ----------------
template <int NC>
__global__ void scatter_kernel(const float* __restrict__ h,
                               const int* __restrict__ src,
                               const int* __restrict__ dst,
                               float* __restrict__ s, int E) {
    constexpr int LPE = NC / 4;
    int lane = threadIdx.x & (LPE - 1);
    int eg = (blockIdx.x * blockDim.x + threadIdx.x) / LPE;
    int estride = (gridDim.x * blockDim.x) / LPE;
    for (int e = eg; e < E; e += estride) {
        int si = __ldg(&src[e]);
        int di = __ldg(&dst[e]);
        float4 v = *(const float4*)(h + (size_t)si * NC + lane * 4);
        red_add_v4(s + (size_t)di * NC + lane * 4, v);
    }
}

// ---- pipelined FFMA2 GEMM: C[M,NC] = A[M,K] @ W[NC,K]^T (+epilogue) --------
// BM=128, BK=16, 256 threads; thread tile 8 rows x NC/16 cols (split-N groups)
// EPI: 0 = plain, 1 = leaky(C + b + s/deg), 2 = C + b + s/deg
template <int NC, int EPI, bool FUSED>
__global__ __launch_bounds__(256, 2)
void gemm_kernel(const float* __restrict__ A, int K,
                 const float* __restrict__ A2,
                 const float* __restrict__ W,
                 const float* __restrict__ bias,
                 const float* __restrict__ sagg,
                 const float* __restrict__ degp,
                 float* __restrict__ C, int M) {
    constexpr int BM = 128, BK = 16;
    constexpr int WPT = NC / 64;      // W float4 loads/thread (2 or 1)
    constexpr int NG  = NC / 64;      // column groups (2 or 1)
    constexpr int CP2 = NC / 32;      // packed col-pairs per thread (4 or 2)
    constexpr int WST = NC + 4;       // Ws row stride (conflict-free)

    __shared__ float As[2][BM][BK + 4];   // row stride 20 floats (80B, 16B-aligned)
    __shared__ float Ws[2][BK][WST];

    int tid = threadIdx.x;
    int tx = tid & 15, ty = tid >> 4;
    int row0 = blockIdx.x * BM;
    int r0 = ty * 8;
    int c0 = tx * 4;

    unsigned long long acc2[8][CP2];
#pragma unroll
    for (int i = 0; i < 8; i++)
#pragma unroll
        for (int j = 0; j < CP2; j++) acc2[i][j] = 0ull;

    float4 ar[2], wr[WPT];
    int nch = K / BK;

    auto ldgA = [&](int ch) {
        int kk = ch * BK;
#pragma unroll
        for (int h = 0; h < 2; h++) {
            int f = tid + h * 256;
            int row = f >> 2;
            int kc = (f & 3) * 4;
            int grow = row0 + row;
            float4 v = make_float4(0.f, 0.f, 0.f, 0.f);
            if (grow < M) {
                if (!FUSED)
                    v = *(const float4*)(A + (size_t)grow * K + kk + kc);
                else if (kk < VT_DIM)
                    v = *(const float4*)(A + (size_t)grow * VT_DIM + kk + kc);
                else
                    v = *(const float4*)(A2 + (size_t)grow * CAT_DIM + (kk - VT_DIM) + kc);
            }
            ar[h] = v;
        }
    };
    auto ldgW = [&](int ch) {
        int kk = ch * BK;
#pragma unroll
        for (int h = 0; h < WPT; h++) {
            int f = tid + h * 256;
            int c = f >> 2;
            int kq = (f & 3) * 4;
            wr[h] = *(const float4*)(W + (size_t)c * K + kk + kq);
        }
    };
    auto sts = [&](int b) {
#pragma unroll
        for (int h = 0; h < 2; h++) {
            int f = tid + h * 256;
            *(float4*)&As[b][f >> 2][(f & 3) * 4] = ar[h];
        }
#pragma unroll
        for (int h = 0; h < WPT; h++) {
            int f = tid + h * 256;
            int c = f >> 2;
            int kq = (f & 3) * 4;
            Ws[b][kq + 0][c] = wr[h].x;
            Ws[b][kq + 1][c] = wr[h].y;
            Ws[b][kq + 2][c] = wr[h].z;
            Ws[b][kq + 3][c] = wr[h].w;
        }
    };
    auto compute = [&](int b) {
#pragma unroll
        for (int k2 = 0; k2 < BK; k2 += 2) {
            ulonglong2 w0[NG], w1[NG];
#pragma unroll
            for (int g = 0; g < NG; g++) {
                w0[g] = *(const ulonglong2*)&Ws[b][k2 + 0][c0 + g * 64];
                w1[g] = *(const ulonglong2*)&Ws[b][k2 + 1][c0 + g * 64];
            }
#pragma unroll
            for (int i = 0; i < 8; i++) {
                float2 t = *(const float2*)&As[b][r0 + i][k2];
                unsigned long long pa0 = pack_dup(t.x);
                unsigned long long pa1 = pack_dup(t.y);
#pragma unroll
                for (int g = 0; g < NG; g++) {
                    ffma2(acc2[i][2 * g + 0], pa0, w0[g].x);
                    ffma2(acc2[i][2 * g + 1], pa0, w0[g].y);
                    ffma2(acc2[i][2 * g + 0], pa1, w1[g].x);
                    ffma2(acc2[i][2 * g + 1], pa1, w1[g].y);
                }
            }
        }
    };

    // prologue
    ldgA(0); ldgW(0);
    sts(0);
    __syncthreads();

    for (int ch = 0; ch < nch; ch++) {
        int nb = ch & 1;
        if (ch + 1 < nch) { ldgA(ch + 1); ldgW(ch + 1); }
        compute(nb);
        if (ch + 1 < nch) sts(1 - nb);
        __syncthreads();
    }

    // epilogue
#pragma unroll
    for (int i = 0; i < 8; i++) {
        int gr = row0 + r0 + i;
        if (gr >= M) continue;
        float dinv = 0.f;
        if (EPI != 0) dinv = 1.0f / fmaxf(degp[gr], 1.0f);
#pragma unroll
        for (int g = 0; g < NG; g++) {
            int gc = c0 + g * 64;
            float4 v;
            unpack2(acc2[i][2 * g + 0], v.x, v.y);
            unpack2(acc2[i][2 * g + 1], v.z, v.w);
            if (EPI != 0) {
                float4 sv = *(const float4*)(sagg + (size_t)gr * NC + gc);
                v.x += bias[gc + 0] + sv.x * dinv;
                v.y += bias[gc + 1] + sv.y * dinv;
                v.z += bias[gc + 2] + sv.z * dinv;
                v.w += bias[gc + 3] + sv.w * dinv;
                if (EPI == 1) {
                    v.x = v.x > 0.f ? v.x : 0.01f * v.x;
                    v.y = v.y > 0.f ? v.y : 0.01f * v.y;
                    v.z = v.z > 0.f ? v.z : 0.01f * v.z;
                    v.w = v.w > 0.f ? v.w : 0.01f * v.w;
                }
            }
            *(float4*)(C + (size_t)gr * NC + gc) = v;
        }
    }
}

// ---------------- launch ----------------
extern "C" void kernel_launch(void* const* d_in, const int* in_sizes, int n_in,
                              void* d_out, int out_size) {
    const float* vt      = (const float*)d_in[0];
    const int*   cat_idx = (const int*)d_in[1];
    const int*   cat_off = (const int*)d_in[2];
    const int*   edge    = (const int*)d_in[3];
    const float* cat_tab = (const float*)d_in[4];
    const float* fuse_w  = (const float*)d_in[5];
    const float* user    = (const float*)d_in[6];
    const float* w1_l    = (const float*)d_in[7];
    const float* b1      = (const float*)d_in[8];
    const float* w1_r    = (const float*)d_in[9];
    const float* w2_l    = (const float*)d_in[10];
    const float* b2      = (const float*)d_in[11];
    const float* w2_r    = (const float*)d_in[12];

    int E = in_sizes[3] / 2;
    const int* src = edge;
    const int* dst = edge + E;
    int tot_idx = in_sizes[1];

    float *x0p, *h1p, *s1p, *x1p, *h2p, *s2p, *catp, *degp;
    cudaGetSymbolAddress((void**)&x0p, g_x0);
    cudaGetSymbolAddress((void**)&h1p, g_h1);
    cudaGetSymbolAddress((void**)&s1p, g_s1);
    cudaGetSymbolAddress((void**)&x1p, g_x1);
    cudaGetSymbolAddress((void**)&h2p, g_h2);
    cudaGetSymbolAddress((void**)&s2p, g_s2);
    cudaGetSymbolAddress((void**)&catp, g_cat);
    cudaGetSymbolAddress((void**)&degp, g_deg);

    const int grid_item = (ITEM_NUM + 127) / 128;   // 391
    const int grid_all  = (NTOT + 127) / 128;       // 782

    // 1. zero scratch
    zero_fill_kernel<<<2048, 256>>>();
    // 2. x0[0:USER] = user
    copy_user_kernel<<<(USER_NUM * HID / 4 + 255) / 256, 256>>>(user);
    // 3. cat embedding bag
    catbag_kernel<<<(ITEM_NUM * 8 + 255) / 256, 256>>>(cat_tab, cat_idx, cat_off, tot_idx);
    // 4. item_feat = [vt | cat] @ fuse_w.T  -> x0[USER:]
    gemm_kernel<128, 0, true><<<grid_item, 256>>>(
        vt, VT_DIM + CAT_DIM, catp, fuse_w, nullptr, nullptr, nullptr,
        x0p + (size_t)USER_NUM * HID, ITEM_NUM);
    // 5. degree
    deg_kernel<<<2048, 256>>>(dst, E);
    // 6. h1 = x0 @ w1_l.T
    gemm_kernel<128, 0, false><<<grid_all, 256>>>(
        x0p, HID, nullptr, w1_l, nullptr, nullptr, nullptr, h1p, NTOT);
    // 7. s1[dst] += h1[src]
    scatter_kernel<128><<<2048, 256>>>(h1p, src, dst, s1p, E);
    // 8. x1 = leaky(s1/deg + b1 + x0 @ w1_r.T)
    gemm_kernel<128, 1, false><<<grid_all, 256>>>(
        x0p, HID, nullptr, w1_r, b1, s1p, degp, x1p, NTOT);
    // 9. h2 = x1 @ w2_l.T
    gemm_kernel<64, 0, false><<<grid_all, 256>>>(
        x1p, HID, nullptr, w2_l, nullptr, nullptr, nullptr, h2p, NTOT);
    // 10. s2[dst] += h2[src]
    scatter_kernel<64><<<2048, 256>>>(h2p, src, dst, s2p, E);
    // 11. out = s2/deg + b2 + x1 @ w2_r.T
    gemm_kernel<64, 2, false><<<grid_all, 256>>>(
        x1p, HID, nullptr, w2_r, b2, s2p, degp, (float*)d_out, NTOT);
}